// round 3
// baseline (speedup 1.0000x reference)
#include <cuda_runtime.h>

// Sizes: x (256,4096) f32, weights (64,64,64) f32, out (256,4096) f32.
// out[b, f*64+n] = sum_c sum_m w[f,c,m] * x[b, c*64 + (n-m) mod 64]
// computed in the 64-point DFT domain with rfft symmetry (33 freqs).

#define NF 33
#define BSZ 256
#define CC 64
#define FF 64

// [k][row] planes. Wf rows = f*64+c (4096), Xf rows = b*64+c (16384),
// S rows = b*64+f (16384).
__device__ float2 g_Wf[NF * FF * CC];
__device__ float2 g_Xf[NF * BSZ * CC];
__device__ float2 g_S [NF * BSZ * FF];

// ---------------------------------------------------------------------------
// Kernel 1: forward rDFT of every length-64 row of w (4096 rows) and x
// (16384 rows). Basis-matrix formulation: Bsm[j][k] = e^{-2*pi*i*j*k/64}
// lives in smem (built from a 64-entry table); lane = frequency k (0..31),
// row values arrive as broadcast float4 global loads. k=32 is a parity sum
// via warp shuffles. 32 rows per CTA (4 per warp), 640 CTAs.
// ---------------------------------------------------------------------------
__global__ void __launch_bounds__(256) k_dft(const float* __restrict__ x,
                                             const float* __restrict__ w) {
    __shared__ float2 Bsm[64][32];   // [j][k]  16 KB
    __shared__ float2 tw[64];

    const int t = threadIdx.x;
    if (t < 64) {
        float s, c;
        sincospif(-(float)t * (1.0f / 32.0f), &s, &c);
        tw[t] = make_float2(c, s);
    }
    __syncthreads();
#pragma unroll
    for (int i = t; i < 2048; i += 256) {
        const int j = i >> 5, k = i & 31;
        Bsm[j][k] = tw[(j * k) & 63];
    }
    __syncthreads();

    const int warp = t >> 5;
    const int lane = t & 31;

#pragma unroll
    for (int rr = 0; rr < 4; rr++) {
        const int row = blockIdx.x * 32 + warp * 4 + rr;   // 0..20479

        const float* src;
        float2* dst;
        int plane;
        if (row < FF * CC) {             // weight rows first
            src = w + row * 64;
            dst = g_Wf + row;
            plane = FF * CC;
        } else {
            const int r = row - FF * CC;
            src = x + r * 64;
            dst = g_Xf + r;
            plane = BSZ * CC;
        }

        // k = 32: sum (-1)^j row[j] via coalesced per-lane loads + reduce
        float p = src[lane] + src[lane + 32];
        if (lane & 1) p = -p;
#pragma unroll
        for (int o = 16; o; o >>= 1) p += __shfl_xor_sync(0xffffffffu, p, o);

        // k = 0..31: basis multiply; row broadcast as float4
        const float4* src4 = (const float4*)src;
        float ar = 0.0f, ai = 0.0f;
#pragma unroll
        for (int g = 0; g < 16; g++) {
            const float4 v = src4[g];
            const float2 b0 = Bsm[4 * g + 0][lane];
            const float2 b1 = Bsm[4 * g + 1][lane];
            const float2 b2 = Bsm[4 * g + 2][lane];
            const float2 b3 = Bsm[4 * g + 3][lane];
            ar = fmaf(v.x, b0.x, ar);  ai = fmaf(v.x, b0.y, ai);
            ar = fmaf(v.y, b1.x, ar);  ai = fmaf(v.y, b1.y, ai);
            ar = fmaf(v.z, b2.x, ar);  ai = fmaf(v.z, b2.y, ai);
            ar = fmaf(v.w, b3.x, ar);  ai = fmaf(v.w, b3.y, ai);
        }
        dst[lane * plane] = make_float2(ar, ai);
        if (lane == 0) dst[32 * plane] = make_float2(p, 0.0f);
    }
}

// ---------------------------------------------------------------------------
// Kernel 2: per-frequency complex GEMM. Grid (4 b-tiles, 33 freqs), 512 thr
// (16 warps -> 4/SMSP for latency hiding). Tile 64b x 64f over 64 c; each
// thread computes 2b x 4f. Xs reads are 2-address broadcasts; Ws pitch 65
// fans the 16 strided f-reads across all 32 banks.
// ---------------------------------------------------------------------------
__global__ void __launch_bounds__(512) k_gemm() {
    extern __shared__ float2 sm[];
    float2* Xs = sm;            // [64][64]   (b-major, pitch 64)
    float2* Ws = sm + 64 * 64;  // [64][65]   (f-major, pitch 65)

    const int k  = blockIdx.y;
    const int b0 = blockIdx.x * 64;
    const float2* gX = g_Xf + k * (BSZ * CC) + b0 * CC;
    const float2* gW = g_Wf + k * (FF * CC);

#pragma unroll
    for (int i = threadIdx.x; i < 4096; i += 512) {
        Xs[i] = gX[i];
        Ws[(i >> 6) * 65 + (i & 63)] = gW[i];
    }
    __syncthreads();

    const int tf = threadIdx.x & 15;   // f = tf + 16*i
    const int tb = threadIdx.x >> 4;   // b = tb + 32*j

    float Sr[2][4] = {}, Si[2][4] = {};
#pragma unroll 4
    for (int c = 0; c < 64; c++) {
        float2 xv[2], wv[4];
#pragma unroll
        for (int j = 0; j < 2; j++) xv[j] = Xs[(tb + 32 * j) * 64 + c];
#pragma unroll
        for (int i = 0; i < 4; i++) wv[i] = Ws[(tf + 16 * i) * 65 + c];
#pragma unroll
        for (int j = 0; j < 2; j++)
#pragma unroll
            for (int i = 0; i < 4; i++) {
                Sr[j][i] = fmaf(xv[j].x, wv[i].x, Sr[j][i]);
                Sr[j][i] = fmaf(-xv[j].y, wv[i].y, Sr[j][i]);
                Si[j][i] = fmaf(xv[j].x, wv[i].y, Si[j][i]);
                Si[j][i] = fmaf(xv[j].y, wv[i].x, Si[j][i]);
            }
    }

    float2* gS = g_S + k * (BSZ * FF) + b0 * FF;
#pragma unroll
    for (int j = 0; j < 2; j++)
#pragma unroll
        for (int i = 0; i < 4; i++)
            gS[(tb + 32 * j) * FF + (tf + 16 * i)] =
                make_float2(Sr[j][i], Si[j][i]);
}

// ---------------------------------------------------------------------------
// Kernel 3: real inverse transform as a tiny GEMM against a constant 33x64
// (complex) matrix built from a 64-entry twiddle table.
//   out[r][n] = sum_k Sr[k][r]*Br[k][n] + Si[k][r]*Bi[k][n]
//   Br[k][n] = s_k * cos(2*pi*k*n/64), Bi[k][n] = -s_k * sin(2*pi*k*n/64)
//   s_k = 1/64 for k in {0,32}, else 2/64.
// 512 CTAs x 256 thr; CTA handles 32 rows, thread = (row, 8-wide n group).
// ---------------------------------------------------------------------------
__global__ void __launch_bounds__(256) k_inv(float* __restrict__ out) {
    __shared__ float2 Ssh[32][NF];   // [row][k]
    __shared__ float2 Bm[NF][64];    // (Br, Bi) interleaved
    __shared__ float2 tw[64];

    const int t = threadIdx.x;
    if (t < 64) {
        float s, c;
        sincospif((float)t * (1.0f / 32.0f), &s, &c);
        tw[t] = make_float2(c, s);
    }
    __syncthreads();
    for (int i = t; i < NF * 64; i += 256) {
        const int k = i >> 6, n = i & 63;
        const float sc = (k == 0 || k == 32) ? (1.0f / 64.0f) : (2.0f / 64.0f);
        const float2 wv = tw[(k * n) & 63];
        Bm[k][n] = make_float2(sc * wv.x, -sc * wv.y);
    }

    const int r0 = blockIdx.x * 32;
    for (int i = t; i < 32 * NF; i += 256) {
        const int rl = i & 31, k = i >> 5;
        Ssh[rl][k] = g_S[k * (BSZ * FF) + r0 + rl];
    }
    __syncthreads();

    const int ng  = t & 7;    // n-group: n = ng*8 .. ng*8+7
    const int row = t >> 3;   // 0..31

    float acc[8] = {0, 0, 0, 0, 0, 0, 0, 0};
    for (int k = 0; k < NF; k++) {
        const float2 sv = Ssh[row][k];
#pragma unroll
        for (int u = 0; u < 8; u++) {
            const float2 b = Bm[k][ng * 8 + u];
            acc[u] = fmaf(sv.x, b.x, acc[u]);
            acc[u] = fmaf(sv.y, b.y, acc[u]);
        }
    }

    float4* o = (float4*)(out + (r0 + row) * 64 + ng * 8);
    o[0] = make_float4(acc[0], acc[1], acc[2], acc[3]);
    o[1] = make_float4(acc[4], acc[5], acc[6], acc[7]);
}

// ---------------------------------------------------------------------------
extern "C" void kernel_launch(void* const* d_in, const int* in_sizes, int n_in,
                              void* d_out, int out_size) {
    const float* x = (const float*)d_in[0];
    const float* w = (const float*)d_in[1];
    // Defensive: identify by element count (x = 1048576, w = 262144).
    if (n_in >= 2 && in_sizes[0] == 64 * 64 * 64) {
        x = (const float*)d_in[1];
        w = (const float*)d_in[0];
    }

    static const size_t gemm_smem = (64 * 64 + 64 * 65) * sizeof(float2); // 66048
    cudaFuncSetAttribute(k_gemm, cudaFuncAttributeMaxDynamicSharedMemorySize,
                         (int)gemm_smem);

    // 20480 rows total (4096 weight rows + 16384 x rows), 32 rows per CTA.
    k_dft<<<640, 256>>>(x, w);
    k_gemm<<<dim3(4, 33), 512, gemm_smem>>>();
    k_inv<<<512, 256>>>((float*)d_out);
}

// round 5
// speedup vs baseline: 2.1504x; 2.1504x over previous
#include <cuda_runtime.h>

// Sizes: x (256,4096) f32, weights (64,64,64) f32, out (256,4096) f32.
// out[b, f*64+n] = sum_c sum_m w[f,c,m] * x[b, c*64 + (n-m) mod 64]
// computed in the 64-point DFT domain with rfft symmetry (33 freqs).

#define NF 33
#define BSZ 256
#define CC 64
#define FF 64

// [k][row] planes. Wf rows = f*64+c (4096), Xf rows = b*64+c (16384),
// S rows = b*64+f (16384).
__device__ float2 g_Wf[NF * FF * CC];
__device__ float2 g_Xf[NF * BSZ * CC];
__device__ float2 g_S [NF * BSZ * FF];

// ---------------------------------------------------------------------------
// Kernel 1: forward rDFT of every length-64 row (4096 w-rows + 16384 x-rows).
// Radix-2 split: e[j] = v[j]+v[j+32], o[j] = v[j]-v[j+32];
//   X[k] = sum_{j<32} (k even ? e[j] : o[j]) * tw[(j*k)&63].
// CTA = 32 rows, warp = 4 rows, lane = frequency k. Outputs staged in smem
// and written coalesced per k-plane. Small loop body -> ~20 live regs.
// ---------------------------------------------------------------------------
__global__ void __launch_bounds__(256) k_dft(const float* __restrict__ x,
                                             const float* __restrict__ w) {
    __shared__ float  esm[32][33];
    __shared__ float  osm[32][33];
    __shared__ float2 Bsm[32][32];    // [j][k]
    __shared__ float2 outsm[33][33];  // [k][rl], pitch 33
    __shared__ float2 tw[64];

    const int t = threadIdx.x;
    if (t < 64) {
        float s, c;
        sincospif(-(float)t * (1.0f / 32.0f), &s, &c);
        tw[t] = make_float2(c, s);
    }
    __syncthreads();
#pragma unroll
    for (int i = t; i < 1024; i += 256) {
        const int j = i >> 5, k = i & 31;
        Bsm[j][k] = tw[(j * k) & 63];
    }

    const int row0 = blockIdx.x * 32;
    const bool isW = row0 < FF * CC;          // 4096 = 128 CTAs * 32, clean split
    const float* src = isW ? (w + row0 * 64) : (x + (row0 - FF * CC) * 64);

    // stage + radix-2 pre-sums
    {
        const int r = t >> 3, q = t & 7;
        const float4* s4 = (const float4*)(src + r * 64);
        const float4 a = s4[q];
        const float4 bq = s4[q + 8];
        esm[r][q * 4 + 0] = a.x + bq.x;  osm[r][q * 4 + 0] = a.x - bq.x;
        esm[r][q * 4 + 1] = a.y + bq.y;  osm[r][q * 4 + 1] = a.y - bq.y;
        esm[r][q * 4 + 2] = a.z + bq.z;  osm[r][q * 4 + 2] = a.z - bq.z;
        esm[r][q * 4 + 3] = a.w + bq.w;  osm[r][q * 4 + 3] = a.w - bq.w;
    }
    __syncthreads();

    const int warp = t >> 5, lane = t & 31;
    const int r0 = warp * 4;
    const float (*usm)[33] = (lane & 1) ? osm : esm;

    float ar0 = 0, ai0 = 0, ar1 = 0, ai1 = 0;
    float ar2 = 0, ai2 = 0, ar3 = 0, ai3 = 0;
#pragma unroll 8
    for (int j = 0; j < 32; j++) {
        const float2 b = Bsm[j][lane];
        const float v0 = usm[r0 + 0][j];
        const float v1 = usm[r0 + 1][j];
        const float v2 = usm[r0 + 2][j];
        const float v3 = usm[r0 + 3][j];
        ar0 = fmaf(v0, b.x, ar0);  ai0 = fmaf(v0, b.y, ai0);
        ar1 = fmaf(v1, b.x, ar1);  ai1 = fmaf(v1, b.y, ai1);
        ar2 = fmaf(v2, b.x, ar2);  ai2 = fmaf(v2, b.y, ai2);
        ar3 = fmaf(v3, b.x, ar3);  ai3 = fmaf(v3, b.y, ai3);
    }
    outsm[lane][r0 + 0] = make_float2(ar0, ai0);
    outsm[lane][r0 + 1] = make_float2(ar1, ai1);
    outsm[lane][r0 + 2] = make_float2(ar2, ai2);
    outsm[lane][r0 + 3] = make_float2(ar3, ai3);

    // k = 32: sum (-1)^j e[j]  (j<32; j and j+32 have equal parity sign)
#pragma unroll
    for (int rr = 0; rr < 4; rr++) {
        float p = esm[r0 + rr][lane];
        if (lane & 1) p = -p;
#pragma unroll
        for (int o = 16; o; o >>= 1) p += __shfl_xor_sync(0xffffffffu, p, o);
        if (lane == 0) outsm[32][r0 + rr] = make_float2(p, 0.0f);
    }
    __syncthreads();

    // coalesced per-plane stores
    float2* base = isW ? g_Wf : g_Xf;
    const int plane = isW ? (FF * CC) : (BSZ * CC);
    const int roff = isW ? row0 : (row0 - FF * CC);
#pragma unroll
    for (int i = t; i < 33 * 32; i += 256) {
        const int k = i >> 5, rl = i & 31;
        base[k * plane + roff + rl] = outsm[k][rl];
    }
}

// ---------------------------------------------------------------------------
// Kernel 2: per-frequency complex GEMM. Grid (4 b-tiles, 33 freqs), 512 thr.
// Tile 64b x 64f over 64 c; each thread computes 2b x 4f.
// ---------------------------------------------------------------------------
__global__ void __launch_bounds__(512) k_gemm() {
    extern __shared__ float2 sm[];
    float2* Xs = sm;            // [64][64]   (b-major, pitch 64)
    float2* Ws = sm + 64 * 64;  // [64][65]   (f-major, pitch 65)

    const int k  = blockIdx.y;
    const int b0 = blockIdx.x * 64;
    const float2* gX = g_Xf + k * (BSZ * CC) + b0 * CC;
    const float2* gW = g_Wf + k * (FF * CC);

#pragma unroll
    for (int i = threadIdx.x; i < 4096; i += 512) {
        Xs[i] = gX[i];
        Ws[(i >> 6) * 65 + (i & 63)] = gW[i];
    }
    __syncthreads();

    const int tf = threadIdx.x & 15;   // f = tf + 16*i
    const int tb = threadIdx.x >> 4;   // b = tb + 32*j

    float Sr[2][4] = {}, Si[2][4] = {};
#pragma unroll 4
    for (int c = 0; c < 64; c++) {
        float2 xv[2], wv[4];
#pragma unroll
        for (int j = 0; j < 2; j++) xv[j] = Xs[(tb + 32 * j) * 64 + c];
#pragma unroll
        for (int i = 0; i < 4; i++) wv[i] = Ws[(tf + 16 * i) * 65 + c];
#pragma unroll
        for (int j = 0; j < 2; j++)
#pragma unroll
            for (int i = 0; i < 4; i++) {
                Sr[j][i] = fmaf(xv[j].x, wv[i].x, Sr[j][i]);
                Sr[j][i] = fmaf(-xv[j].y, wv[i].y, Sr[j][i]);
                Si[j][i] = fmaf(xv[j].x, wv[i].y, Si[j][i]);
                Si[j][i] = fmaf(xv[j].y, wv[i].x, Si[j][i]);
            }
    }

    float2* gS = g_S + k * (BSZ * FF) + b0 * FF;
#pragma unroll
    for (int j = 0; j < 2; j++)
#pragma unroll
        for (int i = 0; i < 4; i++)
            gS[(tb + 32 * j) * FF + (tf + 16 * i)] =
                make_float2(Sr[j][i], Si[j][i]);
}

// ---------------------------------------------------------------------------
// Kernel 3: real inverse transform with n / n+32 symmetry:
//   out[r][n]    = E[r][n] + O[r][n]
//   out[r][n+32] = E[r][n] - O[r][n]      (n < 32)
//   E over even k, O over odd k, Bm[k][n] = (s_k cos(2pi k n/64),
//   -s_k sin(...)), s_k = 1/64 for k in {0,32} else 2/64.
// CTA = 64 rows, thread = (row, 8-wide n-group in lower half). 256 CTAs.
// ---------------------------------------------------------------------------
__global__ void __launch_bounds__(256) k_inv(float* __restrict__ out) {
    __shared__ float2 Ssh[64][NF];   // [row][k]
    __shared__ float2 Bm[NF][32];    // n < 32 only
    __shared__ float2 tw[64];

    const int t = threadIdx.x;
    if (t < 64) {
        float s, c;
        sincospif((float)t * (1.0f / 32.0f), &s, &c);
        tw[t] = make_float2(c, s);
    }
    __syncthreads();
#pragma unroll
    for (int i = t; i < NF * 32; i += 256) {
        const int k = i >> 5, n = i & 31;
        const float sc = (k == 0 || k == 32) ? (1.0f / 64.0f) : (2.0f / 64.0f);
        const float2 wv = tw[(k * n) & 63];
        Bm[k][n] = make_float2(sc * wv.x, -sc * wv.y);
    }

    const int r0 = blockIdx.x * 64;
#pragma unroll
    for (int i = t; i < 64 * NF; i += 256) {
        const int rl = i & 63, k = i >> 6;
        Ssh[rl][k] = g_S[k * (BSZ * FF) + r0 + rl];
    }
    __syncthreads();

    const int ng  = t & 3;    // n = ng*8 .. ng*8+7 (lower half)
    const int row = t >> 2;   // 0..63

    float e[8] = {0, 0, 0, 0, 0, 0, 0, 0};
    float o[8] = {0, 0, 0, 0, 0, 0, 0, 0};
#pragma unroll
    for (int kk = 0; kk < 17; kk++) {          // even k = 0,2,...,32
        const int k = 2 * kk;
        const float2 sv = Ssh[row][k];
#pragma unroll
        for (int u = 0; u < 8; u++) {
            const float2 b = Bm[k][ng * 8 + u];
            e[u] = fmaf(sv.x, b.x, e[u]);
            e[u] = fmaf(sv.y, b.y, e[u]);
        }
    }
#pragma unroll
    for (int kk = 0; kk < 16; kk++) {          // odd k = 1,3,...,31
        const int k = 2 * kk + 1;
        const float2 sv = Ssh[row][k];
#pragma unroll
        for (int u = 0; u < 8; u++) {
            const float2 b = Bm[k][ng * 8 + u];
            o[u] = fmaf(sv.x, b.x, o[u]);
            o[u] = fmaf(sv.y, b.y, o[u]);
        }
    }

    float* obase = out + (r0 + row) * 64 + ng * 8;
    float4* olo = (float4*)obase;
    float4* ohi = (float4*)(obase + 32);
    olo[0] = make_float4(e[0] + o[0], e[1] + o[1], e[2] + o[2], e[3] + o[3]);
    olo[1] = make_float4(e[4] + o[4], e[5] + o[5], e[6] + o[6], e[7] + o[7]);
    ohi[0] = make_float4(e[0] - o[0], e[1] - o[1], e[2] - o[2], e[3] - o[3]);
    ohi[1] = make_float4(e[4] - o[4], e[5] - o[5], e[6] - o[6], e[7] - o[7]);
}

// ---------------------------------------------------------------------------
extern "C" void kernel_launch(void* const* d_in, const int* in_sizes, int n_in,
                              void* d_out, int out_size) {
    const float* x = (const float*)d_in[0];
    const float* w = (const float*)d_in[1];
    // Defensive: identify by element count (x = 1048576, w = 262144).
    if (n_in >= 2 && in_sizes[0] == 64 * 64 * 64) {
        x = (const float*)d_in[1];
        w = (const float*)d_in[0];
    }

    static const size_t gemm_smem = (64 * 64 + 64 * 65) * sizeof(float2); // 66048
    cudaFuncSetAttribute(k_gemm, cudaFuncAttributeMaxDynamicSharedMemorySize,
                         (int)gemm_smem);

    // 20480 rows total (4096 weight rows + 16384 x rows), 32 rows per CTA.
    k_dft<<<640, 256>>>(x, w);
    k_gemm<<<dim3(4, 33), 512, gemm_smem>>>();
    k_inv<<<256, 256>>>((float*)d_out);
}